// round 16
// baseline (speedup 1.0000x reference)
#include <cuda_runtime.h>

// ReservoirRNNCell: out = tanh(x@W_ih^T + b + softmax_h(W_hh*mask/tau + gumbel(u)) @ h_prev)
// Identity: exp(logit - log(-log u)) = exp(logit)/(-ln u); ln2 cancels in the ratio,
// so weight = E[o,h] * rcp(lg2(u)).
// B=16, I=1024, H=2048. One block per o: 2048 blocks x 512 threads (warp = batch).
// R16: DEEP cp.async staging for the u-stream: 4-iter chunks (64B/thread) x 3-stage
// ring, issued 2 chunks ahead -> 128B/thread prefetch distance (2x the register
// file's ~64B ceiling that pinned every previous variant at ~5.5 TB/s).
// Tuning log: (256,6)=40r 56.6/56.1 | (256,7)=32r 63.7 | shallow cp.async 64.2 |
//   dual-stream 48r 60.4 | 512thr 1-blk/o 56.0ncu DRAM70.8% | reg-prefetch d2: no change

#define HN 2048
#define IN 1024
#define BN 16
#define THREADS 512
#define NITER (HN / 128)          // 16 loop iterations per warp
#define CHUNK 4                   // iterations per pipeline chunk
#define NCHUNK (NITER / CHUNK)    // 4 chunks
#define NSTAGE 3                  // ring slots

__device__ __forceinline__ float fast_lg2(float x) {
    float r; asm("lg2.approx.f32 %0, %1;" : "=f"(r) : "f"(x)); return r;
}
__device__ __forceinline__ float fast_rcp(float x) {
    float r; asm("rcp.approx.f32 %0, %1;" : "=f"(r) : "f"(x)); return r;
}
__device__ __forceinline__ float fast_ex2(float x) {
    float r; asm("ex2.approx.f32 %0, %1;" : "=f"(r) : "f"(x)); return r;
}
__device__ __forceinline__ unsigned smem_u32(const void* p) {
    unsigned a;
    asm("{ .reg .u64 t; cvta.to.shared.u64 t, %1; cvt.u32.u64 %0, t; }" : "=r"(a) : "l"(p));
    return a;
}
__device__ __forceinline__ void cp_async16(unsigned saddr, const void* gaddr) {
    asm volatile("cp.async.cg.shared.global [%0], [%1], 16;" :: "r"(saddr), "l"(gaddr));
}
__device__ __forceinline__ void cp_commit() {
    asm volatile("cp.async.commit_group;");
}
template <int N>
__device__ __forceinline__ void cp_wait() {
    asm volatile("cp.async.wait_group %0;" :: "n"(N));
}
__device__ __forceinline__ float4 lds128(unsigned saddr) {
    float4 v;
    asm volatile("ld.shared.v4.f32 {%0,%1,%2,%3}, [%4];"
                 : "=f"(v.x), "=f"(v.y), "=f"(v.z), "=f"(v.w) : "r"(saddr));
    return v;
}

// L(u) ~ lg2(u) (negative). MUFU lg2 has ~2^-22 ABSOLUTE error -> unbounded RELATIVE
// error as u->1, and those elements carry the largest softmax weights. For u>0.999
// use the 1-term series L = -log2(e)*(1-u) as a single FFMA (exact product, one
// rounding, no cancellation hazard). Series rel err <= t/2 <= 5e-4 on that 0.1%
// tail; MUFU path rel err at the threshold ~1.7e-4. Both well under the 1e-3 budget.
__device__ __forceinline__ float log_sel(float u) {
    const float PL2E = 1.4426950408889634f;   // +log2(e)
    const float NL2E = -1.4426950408889634f;  // -log2(e)
    float lg = fast_lg2(u);
    float p  = fmaf(u, PL2E, NL2E);           // = -log2(e)*(1-u)
    return (u > 0.999f) ? p : lg;
}

__global__ __launch_bounds__(THREADS, 2)
void reservoir_cell_kernel(
    const float* __restrict__ x_t,        // [B, I]
    const float* __restrict__ h_prev,     // [B, H]
    const float* __restrict__ W_ih_w,     // [H, I]
    const float* __restrict__ W_ih_b,     // [H]
    const float* __restrict__ W_hh,       // [H, H]
    const float* __restrict__ temperature,// [1]
    const float* __restrict__ hh_mask,    // [H, H]
    const float* __restrict__ u_noise,    // [B, H, H]
    float* __restrict__ out)              // [B, H]
{
    __shared__ float wih_s[IN];   // 4 KB
    __shared__ float e_s[HN];     // 8 KB
    extern __shared__ __align__(16) float4 uring[];  // NSTAGE*CHUNK*THREADS float4 = 96 KB

    const int o    = blockIdx.x;                  // output neuron
    const int tid  = threadIdx.x;
    const int b    = tid >> 5;                    // warp id -> batch index (0..15)
    const int lane = tid & 31;

    const float tau   = fmaxf(temperature[0], 1e-3f);
    const float scale = 1.4426950408889634f / tau;   // log2(e)/tau

    // ---- Phase A (cooperative): cache W_ih[o,:] and E[h] = exp2(W_hh[o,h]*mask[o,h]*scale) ----
    {
        const float4* wih4 = (const float4*)(W_ih_w + (size_t)o * IN);
#pragma unroll
        for (int i = tid; i < IN / 4; i += THREADS)
            ((float4*)wih_s)[i] = __ldcs(&wih4[i]);

        const float4* whh4 = (const float4*)(W_hh    + (size_t)o * HN);
        const float4* msk4 = (const float4*)(hh_mask + (size_t)o * HN);
#pragma unroll
        for (int i = tid; i < HN / 4; i += THREADS) {
            float4 wv = __ldcs(&whh4[i]);
            float4 mv = __ldcs(&msk4[i]);
            float4 ev;
            ev.x = fast_ex2(wv.x * mv.x * scale);
            ev.y = fast_ex2(wv.y * mv.y * scale);
            ev.z = fast_ex2(wv.z * mv.z * scale);
            ev.w = fast_ex2(wv.w * mv.w * scale);
            ((float4*)e_s)[i] = ev;
        }
    }
    __syncthreads();

    // ---- Phase B (per warp, batch b): dot(x[b,:], W_ih[o,:]) ----
    float icp = 0.0f;
    {
        const float4* x4 = (const float4*)(x_t + (size_t)b * IN) + lane;
        const float4* w4 = (const float4*)wih_s + lane;
#pragma unroll
        for (int k = 0; k < IN / 128; k++) {
            float4 xv = x4[k * 32];
            float4 wv = w4[k * 32];
            icp = fmaf(xv.x, wv.x, icp);
            icp = fmaf(xv.y, wv.y, icp);
            icp = fmaf(xv.z, wv.z, icp);
            icp = fmaf(xv.w, wv.w, icp);
        }
    }

    // ---- Phase C: u streamed via deep cp.async ring.
    // Slot layout: uring[((s*CHUNK + i)*THREADS) + tid]; each thread copies and
    // reads ONLY its own 16B lanes -> per-thread wait_group, zero barriers.
    float num0 = 0.0f, den0 = 0.0f, num1 = 0.0f, den1 = 0.0f;
    const float4* u4 = (const float4*)(u_noise + ((size_t)(b * HN + o)) * HN) + lane;
    const float4* h4 = (const float4*)(h_prev + (size_t)b * HN) + lane;
    const float4* e4 = (const float4*)e_s + lane;

    const unsigned rb = smem_u32(uring) + (unsigned)tid * 16u;
    // smem addr of (slot s, iter i): rb + (s*CHUNK + i)*THREADS*16

    // Prologue: chunks 0,1 into slots 0,1 (one commit group per chunk)
#pragma unroll
    for (int c = 0; c < 2; c++) {
#pragma unroll
        for (int i = 0; i < CHUNK; i++)
            cp_async16(rb + (unsigned)((c * CHUNK + i) * THREADS) * 16u,
                       &u4[(c * CHUNK + i) * 32]);
        cp_commit();
    }

#pragma unroll
    for (int c = 0; c < NCHUNK; c++) {
        // Issue chunk c+2 BEFORE waiting on chunk c: distance stays 2 chunks (128B/thr)
        if (c + 2 < NCHUNK) {
            const int s = (c + 2) % NSTAGE;
#pragma unroll
            for (int i = 0; i < CHUNK; i++)
                cp_async16(rb + (unsigned)((s * CHUNK + i) * THREADS) * 16u,
                           &u4[((c + 2) * CHUNK + i) * 32]);
            cp_commit();
        }
        // pending groups allowed = committed(min(c+3,4)) - needed(c+1)
        if (c == 0)      cp_wait<2>();
        else if (c == 1) cp_wait<2>();
        else if (c == 2) cp_wait<1>();
        else             cp_wait<0>();

        const int s = c % NSTAGE;
#pragma unroll
        for (int i = 0; i < CHUNK; i++) {
            const int k = c * CHUNK + i;
            float4 uu = lds128(rb + (unsigned)((s * CHUNK + i) * THREADS) * 16u);
            float4 hh = h4[k * 32];               // L1-resident
            float4 ee = e4[k * 32];               // smem

            float wx = ee.x * fast_rcp(log_sel(uu.x));
            float wy = ee.y * fast_rcp(log_sel(uu.y));
            float wz = ee.z * fast_rcp(log_sel(uu.z));
            float ww = ee.w * fast_rcp(log_sel(uu.w));

            den0 += wx; num0 = fmaf(wx, hh.x, num0);
            den1 += wy; num1 = fmaf(wy, hh.y, num1);
            den0 += wz; num0 = fmaf(wz, hh.z, num0);
            den1 += ww; num1 = fmaf(ww, hh.w, num1);
        }
    }
    float num = num0 + num1;
    float den = den0 + den1;

    // ---- warp reduction of (icp, num, den) ----
#pragma unroll
    for (int off = 16; off; off >>= 1) {
        icp += __shfl_xor_sync(0xFFFFFFFFu, icp, off);
        num += __shfl_xor_sync(0xFFFFFFFFu, num, off);
        den += __shfl_xor_sync(0xFFFFFFFFu, den, off);
    }

    if (lane == 0) {
        float contrib = num / den;     // both negative -> correct positive ratio
        out[b * HN + o] = tanhf(icp + W_ih_b[o] + contrib);
    }
}

extern "C" void kernel_launch(void* const* d_in, const int* in_sizes, int n_in,
                              void* d_out, int out_size) {
    const float* x_t     = (const float*)d_in[0];
    const float* h_prev  = (const float*)d_in[1];
    const float* W_ih_w  = (const float*)d_in[2];
    const float* W_ih_b  = (const float*)d_in[3];
    const float* W_hh    = (const float*)d_in[4];
    const float* temp    = (const float*)d_in[5];
    const float* hh_mask = (const float*)d_in[6];
    const float* u_noise = (const float*)d_in[7];
    float* out = (float*)d_out;

    const int ring_bytes = NSTAGE * CHUNK * THREADS * 16;   // 96 KB
    cudaFuncSetAttribute(reservoir_cell_kernel,
                         cudaFuncAttributeMaxDynamicSharedMemorySize, ring_bytes);
    reservoir_cell_kernel<<<HN, THREADS, ring_bytes>>>(
        x_t, h_prev, W_ih_w, W_ih_b, W_hh, temp, hh_mask, u_noise, out);
}

// round 17
// speedup vs baseline: 1.2819x; 1.2819x over previous
#include <cuda_runtime.h>

// ReservoirRNNCell: out = tanh(x@W_ih^T + b + softmax_h(W_hh*mask/tau + gumbel(u)) @ h_prev)
// Identity: exp(logit - log(-log u)) = exp(logit)/(-ln u); ln2 cancels in the ratio,
// so weight = E[o,h] * rcp(lg2(u)).
// B=16, I=1024, H=2048. One block per o: 2048 blocks x 512 threads (warp = batch).
// R17: guard folded into fmin (concavity: lg2(u) <= -log2e*(1-u) always, so fmin
// reproduces the exact path and clips only MUFU's upward error near u->1).
// Tuning log: (256,6)=40r 56.6/56.1 | (256,7)=32r 63.7 | cp.async shallow 64.2 /
//   deep 71.6 (reg+occ blowup) | dual-stream 60.4 | reg-prefetch d2: no change |
//   512thr 1-blk/o 40r: ncu 56.0us DRAM 70.8% (base)

#define HN 2048
#define IN 1024
#define BN 16
#define THREADS 512

__device__ __forceinline__ float fast_lg2(float x) {
    float r; asm("lg2.approx.f32 %0, %1;" : "=f"(r) : "f"(x)); return r;
}
__device__ __forceinline__ float fast_rcp(float x) {
    float r; asm("rcp.approx.f32 %0, %1;" : "=f"(r) : "f"(x)); return r;
}
__device__ __forceinline__ float fast_ex2(float x) {
    float r; asm("ex2.approx.f32 %0, %1;" : "=f"(r) : "f"(x)); return r;
}

// L(u) ~ lg2(u) (negative). MUFU lg2 has ~2^-22 ABSOLUTE error -> unbounded
// RELATIVE error as u->1 (largest softmax weights). Fix via fmin with the
// 1-term bound p = -log2e*(1-u) (single FFMA; p<0 since u<=1-2^-24):
//   - exact math: lg2(u) <= p (concavity of ln), so fmin == lg2. identical.
//   - MUFU errs UP near 1 (could cross 0): fmin clips to p, rel err <= t/2 <= 5e-4.
//   - MUFU errs DOWN: rel err <= 2.4e-7/|L| <= ~3e-4 at the crossover (u~0.9994).
// Guarantees L < 0 unconditionally. One FMNMX instead of FSETP+FSEL.
__device__ __forceinline__ float log_sel(float u) {
    const float PL2E = 1.4426950408889634f;   // +log2(e)
    const float NL2E = -1.4426950408889634f;  // -log2(e)
    return fminf(fast_lg2(u), fmaf(u, PL2E, NL2E));
}

__global__ __launch_bounds__(THREADS, 3)
void reservoir_cell_kernel(
    const float* __restrict__ x_t,        // [B, I]
    const float* __restrict__ h_prev,     // [B, H]
    const float* __restrict__ W_ih_w,     // [H, I]
    const float* __restrict__ W_ih_b,     // [H]
    const float* __restrict__ W_hh,       // [H, H]
    const float* __restrict__ temperature,// [1]
    const float* __restrict__ hh_mask,    // [H, H]
    const float* __restrict__ u_noise,    // [B, H, H]
    float* __restrict__ out)              // [B, H]
{
    __shared__ float wih_s[IN];   // W_ih row for this o (4 KB)
    __shared__ float e_s[HN];     // exp(logits[o,:]) (8 KB)

    const int o    = blockIdx.x;                  // output neuron
    const int tid  = threadIdx.x;
    const int b    = tid >> 5;                    // warp id -> batch index (0..15)
    const int lane = tid & 31;

    const float tau   = fmaxf(temperature[0], 1e-3f);
    const float scale = 1.4426950408889634f / tau;   // log2(e)/tau

    // ---- Phase A (cooperative): cache W_ih[o,:] and E[h] = exp2(W_hh[o,h]*mask[o,h]*scale) ----
    // One block per o: W_hh/mask rows read exactly once chip-wide; E computed once.
    {
        const float4* wih4 = (const float4*)(W_ih_w + (size_t)o * IN);
#pragma unroll
        for (int i = tid; i < IN / 4; i += THREADS)
            ((float4*)wih_s)[i] = __ldcs(&wih4[i]);

        const float4* whh4 = (const float4*)(W_hh    + (size_t)o * HN);
        const float4* msk4 = (const float4*)(hh_mask + (size_t)o * HN);
#pragma unroll
        for (int i = tid; i < HN / 4; i += THREADS) {
            float4 wv = __ldcs(&whh4[i]);
            float4 mv = __ldcs(&msk4[i]);
            float4 ev;
            ev.x = fast_ex2(wv.x * mv.x * scale);
            ev.y = fast_ex2(wv.y * mv.y * scale);
            ev.z = fast_ex2(wv.z * mv.z * scale);
            ev.w = fast_ex2(wv.w * mv.w * scale);
            ((float4*)e_s)[i] = ev;
        }
    }
    __syncthreads();

    // ---- Phase B (per warp, batch b): dot(x[b,:], W_ih[o,:]) ----
    float icp = 0.0f;
    {
        const float4* x4 = (const float4*)(x_t + (size_t)b * IN) + lane;
        const float4* w4 = (const float4*)wih_s + lane;
#pragma unroll
        for (int k = 0; k < IN / 128; k++) {
            float4 xv = x4[k * 32];
            float4 wv = w4[k * 32];
            icp = fmaf(xv.x, wv.x, icp);
            icp = fmaf(xv.y, wv.y, icp);
            icp = fmaf(xv.z, wv.z, icp);
            icp = fmaf(xv.w, wv.w, icp);
        }
    }

    // ---- Phase C (per warp): softmax-weighted sum over h; w = E[h]*rcp(L(u)) ----
    float num0 = 0.0f, den0 = 0.0f, num1 = 0.0f, den1 = 0.0f;
    const float4* u4 = (const float4*)(u_noise + ((size_t)(b * HN + o)) * HN) + lane;
    const float4* h4 = (const float4*)(h_prev + (size_t)b * HN) + lane;
    const float4* e4 = (const float4*)e_s + lane;

#pragma unroll
    for (int k = 0; k < HN / 128; k++) {          // 16 iterations, imm offsets
        float4 uu = __ldcs(&u4[k * 32]);          // streaming 256 MB: evict-first
        float4 hh = h4[k * 32];                   // 128 KB table: L1-resident
        float4 ee = e4[k * 32];                   // smem

        float wx = ee.x * fast_rcp(log_sel(uu.x));
        float wy = ee.y * fast_rcp(log_sel(uu.y));
        float wz = ee.z * fast_rcp(log_sel(uu.z));
        float ww = ee.w * fast_rcp(log_sel(uu.w));

        den0 += wx; num0 = fmaf(wx, hh.x, num0);
        den1 += wy; num1 = fmaf(wy, hh.y, num1);
        den0 += wz; num0 = fmaf(wz, hh.z, num0);
        den1 += ww; num1 = fmaf(ww, hh.w, num1);
    }
    float num = num0 + num1;
    float den = den0 + den1;

    // ---- warp reduction of (icp, num, den) ----
#pragma unroll
    for (int off = 16; off; off >>= 1) {
        icp += __shfl_xor_sync(0xFFFFFFFFu, icp, off);
        num += __shfl_xor_sync(0xFFFFFFFFu, num, off);
        den += __shfl_xor_sync(0xFFFFFFFFu, den, off);
    }

    if (lane == 0) {
        float contrib = num / den;     // both negative -> correct positive ratio
        out[b * HN + o] = tanhf(icp + W_ih_b[o] + contrib);
    }
}

extern "C" void kernel_launch(void* const* d_in, const int* in_sizes, int n_in,
                              void* d_out, int out_size) {
    const float* x_t     = (const float*)d_in[0];
    const float* h_prev  = (const float*)d_in[1];
    const float* W_ih_w  = (const float*)d_in[2];
    const float* W_ih_b  = (const float*)d_in[3];
    const float* W_hh    = (const float*)d_in[4];
    const float* temp    = (const float*)d_in[5];
    const float* hh_mask = (const float*)d_in[6];
    const float* u_noise = (const float*)d_in[7];
    float* out = (float*)d_out;

    reservoir_cell_kernel<<<HN, THREADS>>>(
        x_t, h_prev, W_ih_w, W_ih_b, W_hh, temp, hh_mask, u_noise, out);
}